// round 16
// baseline (speedup 1.0000x reference)
#include <cuda_runtime.h>
#include <cuda_bf16.h>
#include <cuda_fp16.h>

#define NN   50000
#define NE   800000
#define FIN  128
#define FOUT 64
#define SLOPE 0.2f
#define SCAN_NB ((NN + 255) / 256)   // 196

// ---------------- scratch (__device__ globals; no allocations allowed) -----
__device__ __align__(256) float g_h[(size_t)NN * FOUT]; // h fp32, 256B/row
__device__ float    g_asrc[NN];          // h . att_src (fp32)
__device__ float4   g_dinfo[NN];         // (a_dst, sl, start_bits, unused)
__device__ int      g_cnt[NN];           // in-degree (zeroed by agg each run)
__device__ unsigned g_rkd[NE];           // (dst<<16) | rank
__device__ uint2    g_ep[NE];            // per-edge (src, p) dst-sorted
__device__ unsigned g_state[SCAN_NB];    // lookback: state<<30 | value

__device__ __forceinline__ float leaky(float v) { return v > 0.f ? v : SLOPE * v; }

// packed f32x2 helpers (FFMA2 is PTX-only; ptxas never auto-fuses)
__device__ __forceinline__ long long pk2(float lo, float hi) {
    long long r;
    asm("mov.b64 %0, {%1,%2};" : "=l"(r) : "f"(lo), "f"(hi));
    return r;
}
__device__ __forceinline__ void unpk2(long long v, float& lo, float& hi) {
    asm("mov.b64 {%0,%1}, %2;" : "=f"(lo), "=f"(hi) : "l"(v));
}
__device__ __forceinline__ long long ffma2(long long a, long long b, long long c) {
    long long d;
    asm("fma.rn.f32x2 %0, %1, %2, %3;" : "=l"(d) : "l"(a), "l"(b), "l"(c));
    return d;
}

// ---------------------------------------------------------------------------
// K1: dst histogram, 2 edges/thread (int2 loads, 2 independent chains).
//     Stores (dst<<16 | rank). Block 0 resets lookback state.
// ---------------------------------------------------------------------------
__global__ __launch_bounds__(256) void k_count(const int* __restrict__ ei)
{
    if (blockIdx.x == 0 && threadIdx.x < SCAN_NB) g_state[threadIdx.x] = 0;
    int t = blockIdx.x * blockDim.x + threadIdx.x;
    if (t >= NE / 2) return;
    int2 dd = ((const int2*)(ei + NE))[t];
    unsigned r0 = (unsigned)atomicAdd(&g_cnt[dd.x], 1);
    unsigned r1 = (unsigned)atomicAdd(&g_cnt[dd.y], 1);
    int i = t * 2;
    g_rkd[i]     = ((unsigned)dd.x << 16) | (r0 & 0xffffu);
    g_rkd[i + 1] = ((unsigned)dd.y << 16) | (r1 & 0xffffu);
}

// ---------------------------------------------------------------------------
// K2: h = x @ W (packed f32x2 FMAs, 4 rows/warp, 128 threads).
//     Epilogue: fp32 h row, a_src, dst info (a_dst, sl).
// ---------------------------------------------------------------------------
#define GEMM_ROWS 16          // rows per block (4 warps x 4 rows)
__global__ __launch_bounds__(128) void k_gemm(
    const float* __restrict__ x, const float* __restrict__ W,
    const float* __restrict__ att_src, const float* __restrict__ att_dst)
{
    __shared__ long long Wsh[FIN * 32];        // 32 KB
    __shared__ long long Xd[GEMM_ROWS * FIN];  // 16 KB: x duplicated (v,v)

    int tid = threadIdx.x;
    int row0 = blockIdx.x * GEMM_ROWS;

    const float2* W2 = (const float2*)W;
    for (int idx = tid; idx < FIN * 32; idx += 128) {
        float2 wv = W2[idx];
        Wsh[idx] = pk2(wv.x, wv.y);
    }
    for (int idx = tid; idx < GEMM_ROWS * 32; idx += 128) {
        int r = idx >> 5, c = idx & 31;
        int row = row0 + r;
        float4 v = (row < NN) ? ((const float4*)(x + (size_t)row * FIN))[c]
                              : make_float4(0.f, 0.f, 0.f, 0.f);
        long long* dst = &Xd[r * FIN + c * 4];
        dst[0] = pk2(v.x, v.x); dst[1] = pk2(v.y, v.y);
        dst[2] = pk2(v.z, v.z); dst[3] = pk2(v.w, v.w);
    }
    __syncthreads();

    int lane = tid & 31, w = tid >> 5;
    float2 as2 = ((const float2*)att_src)[lane];
    float2 ad2 = ((const float2*)att_dst)[lane];

    long long acc[4] = {0, 0, 0, 0};
    #pragma unroll 4
    for (int k = 0; k < FIN; k += 2) {
        long long w0 = Wsh[k * 32 + lane];
        long long w1 = Wsh[(k + 1) * 32 + lane];
        #pragma unroll
        for (int r = 0; r < 4; r++) {
            longlong2 xx = *(const longlong2*)&Xd[(w * 4 + r) * FIN + k];
            acc[r] = ffma2(xx.x, w0, acc[r]);
            acc[r] = ffma2(xx.y, w1, acc[r]);
        }
    }

    #pragma unroll
    for (int r = 0; r < 4; r++) {
        int row = row0 + w * 4 + r;
        if (row >= NN) continue;
        float a0, a1; unpk2(acc[r], a0, a1);
        ((float2*)(g_h + (size_t)row * FOUT))[lane] = make_float2(a0, a1);
        float ps = a0 * as2.x + a1 * as2.y;
        float pd = a0 * ad2.x + a1 * ad2.y;
        #pragma unroll
        for (int off = 16; off; off >>= 1) {
            ps += __shfl_xor_sync(0xffffffffu, ps, off);
            pd += __shfl_xor_sync(0xffffffffu, pd, off);
        }
        if (lane == 0) {
            g_asrc[row] = ps;
            *(float2*)&g_dinfo[row] = make_float2(pd, leaky(ps + pd));
        }
    }
}

// ---------------------------------------------------------------------------
// K3: single-pass exclusive scan (decoupled lookback), 196 blocks.
//     Writes start into g_dinfo[idx].z (int bits).
// ---------------------------------------------------------------------------
__global__ __launch_bounds__(256) void k_scan()
{
    __shared__ int sm[256];
    __shared__ int s_prefix;
    int t = threadIdx.x, b = blockIdx.x;
    int idx = b * 256 + t;
    int v = (idx < NN) ? g_cnt[idx] : 0;
    sm[t] = v;
    __syncthreads();
    #pragma unroll
    for (int off = 1; off < 256; off <<= 1) {
        int u = (t >= off) ? sm[t - off] : 0;
        __syncthreads();
        sm[t] += u;
        __syncthreads();
    }
    int incl = sm[t];
    int agg  = sm[255];

    if (t == 0) {
        if (b == 0) {
            atomicExch(&g_state[0], (2u << 30) | (unsigned)agg);
            s_prefix = 0;
        } else {
            atomicExch(&g_state[b], (1u << 30) | (unsigned)agg);
            int pre = 0, j = b - 1;
            while (true) {
                unsigned s = atomicAdd(&g_state[j], 0u);
                unsigned st = s >> 30;
                if (st == 0u) continue;
                pre += (int)(s & 0x3fffffffu);
                if (st == 2u) break;
                j--;
            }
            s_prefix = pre;
            atomicExch(&g_state[b], (2u << 30) | (unsigned)(pre + agg));
        }
    }
    __syncthreads();
    if (idx < NN) *(int*)&g_dinfo[idx].z = s_prefix + incl - v;
}

// ---------------------------------------------------------------------------
// K4: scatter resolved (src, p) records, 2 edges/thread (2 indep chains).
// ---------------------------------------------------------------------------
__global__ __launch_bounds__(256) void k_scatter(const int* __restrict__ ei)
{
    int t = blockIdx.x * blockDim.x + threadIdx.x;
    if (t >= NE / 2) return;
    int2  ss = ((const int2*)ei)[t];
    uint2 rd = ((const uint2*)g_rkd)[t];
    int d0 = (int)(rd.x >> 16), r0 = (int)(rd.x & 0xffffu);
    int d1 = (int)(rd.y >> 16), r1 = (int)(rd.y & 0xffffu);
    float4 di0 = g_dinfo[d0];
    float4 di1 = g_dinfo[d1];
    float as0 = g_asrc[ss.x];
    float as1 = g_asrc[ss.y];
    float p0 = __expf(leaky(as0 + di0.x) - di0.y);
    float p1 = __expf(leaky(as1 + di1.x) - di1.y);
    g_ep[__float_as_int(di0.z) + r0] = make_uint2((unsigned)ss.x, __float_as_uint(p0));
    g_ep[__float_as_int(di1.z) + r1] = make_uint2((unsigned)ss.y, __float_as_uint(p1));
}

// ---------------------------------------------------------------------------
// K5: 16 lanes per dst node (2 nodes/warp), fp32 h, pipelined gathers:
//     chunk u+1's 4 LDG.128 issued before chunk u's FMAs (8 loads in flight).
//     ssum starts at 1 (self loop), acc starts at h[node]. Zeroes g_cnt.
// ---------------------------------------------------------------------------
__global__ __launch_bounds__(256) void k_agg(float* __restrict__ out,
                                             const float* __restrict__ bias)
{
    int gid = (blockIdx.x * 256 + threadIdx.x) >> 4;   // node id
    int lane = threadIdx.x & 31;
    int fl = lane & 15;                                // feature quad 0..15
    int gsel = lane & 16;                              // group base lane
    bool live = (gid < NN);
    int node = live ? gid : (NN - 1);

    float4 di = g_dinfo[node];
    int beg = __float_as_int(di.z);
    int cnt = g_cnt[node];

    float ssum = 1.f;                                  // self loop
    float4 acc = ((const float4*)(g_h + (size_t)node * FOUT))[fl];

    // prefetch batch 0 of (src, p)
    uint2 ev = make_uint2(0u, 0u);
    if (cnt > 0 && fl < cnt) ev = g_ep[beg + fl];

    for (int base = 0; base < cnt; base += 16) {
        int nb = cnt - base; if (nb > 16) nb = 16;
        unsigned s = ev.x;
        float p = __uint_as_float(ev.y);
        if (fl >= nb) { s = 0u; p = 0.f; }

        // prefetch next batch of (src, p)
        ev = make_uint2(0u, 0u);
        int nxt = base + 16;
        if (nxt < cnt && fl < cnt - nxt) ev = g_ep[beg + nxt + fl];

        // pipeline: preload chunk 0
        float4 hb[4]; float pc[4];
        #pragma unroll
        for (int u = 0; u < 4; u++) {
            unsigned sl0 = __shfl_sync(0xffffffffu, s, gsel | u, 32);
            pc[u]        = __shfl_sync(0xffffffffu, p, gsel | u, 32);
            hb[u] = ((const float4*)(g_h + (size_t)sl0 * FOUT))[fl];
        }
        int nch = (nb + 3) >> 2;
        for (int c = 1; c <= nch; c++) {
            float4 hn[4]; float pn[4];
            if (c < nch) {
                #pragma unroll
                for (int u = 0; u < 4; u++) {
                    int j = c * 4 + u;
                    unsigned sl0 = __shfl_sync(0xffffffffu, s, gsel | j, 32);
                    pn[u]        = __shfl_sync(0xffffffffu, p, gsel | j, 32);
                    hn[u] = ((const float4*)(g_h + (size_t)sl0 * FOUT))[fl];
                }
            }
            #pragma unroll
            for (int u = 0; u < 4; u++) {
                float pv = pc[u];                      // 0 for padded edges
                ssum += pv;
                acc.x += pv * hb[u].x; acc.y += pv * hb[u].y;
                acc.z += pv * hb[u].z; acc.w += pv * hb[u].w;
            }
            if (c < nch) {
                #pragma unroll
                for (int u = 0; u < 4; u++) { hb[u] = hn[u]; pc[u] = pn[u]; }
            }
        }
    }

    float inv = 1.f / ssum;
    if (live) {
        float4 bv = ((const float4*)bias)[fl];
        float4 r = make_float4(acc.x * inv + bv.x, acc.y * inv + bv.y,
                               acc.z * inv + bv.z, acc.w * inv + bv.w);
        ((float4*)(out + (size_t)node * FOUT))[fl] = r;
        if (fl == 0) g_cnt[node] = 0;                  // ready for next run
    }
}

// ---------------------------------------------------------------------------
extern "C" void kernel_launch(void* const* d_in, const int* in_sizes, int n_in,
                              void* d_out, int out_size)
{
    const float* x    = (const float*)d_in[0];
    const int*   ei   = (const int*)  d_in[1];   // [2, NE]: row0=src, row1=dst
    const float* W    = (const float*)d_in[2];
    const float* asrc = (const float*)d_in[3];
    const float* adst = (const float*)d_in[4];
    const float* bias = (const float*)d_in[5];
    float* out = (float*)d_out;

    static cudaStream_t s1 = nullptr;
    static cudaEvent_t ev_fork = nullptr, ev_join = nullptr;
    if (s1 == nullptr) {
        cudaStreamCreateWithFlags(&s1, cudaStreamNonBlocking);
        cudaEventCreateWithFlags(&ev_fork, cudaEventDisableTiming);
        cudaEventCreateWithFlags(&ev_join, cudaEventDisableTiming);
    }

    // fork: GEMM (x,W only) on s1, concurrent with count+scan (ei only)
    cudaEventRecord(ev_fork, 0);
    cudaStreamWaitEvent(s1, ev_fork, 0);
    k_gemm<<<(NN + GEMM_ROWS - 1) / GEMM_ROWS, 128, 0, s1>>>(x, W, asrc, adst);
    cudaEventRecord(ev_join, s1);

    k_count<<<(NE / 2 + 255) / 256, 256>>>(ei);
    k_scan <<<SCAN_NB, 256>>>();

    cudaStreamWaitEvent(0, ev_join, 0);          // scatter needs GEMM outputs
    k_scatter<<<(NE / 2 + 255) / 256, 256>>>(ei);
    k_agg<<<(NN * 16 + 255) / 256, 256>>>(out, bias);
}

// round 17
// speedup vs baseline: 1.1124x; 1.1124x over previous
#include <cuda_runtime.h>
#include <cuda_bf16.h>
#include <cuda_fp16.h>

#define NN   50000
#define NE   800000
#define FIN  128
#define FOUT 64
#define SLOPE 0.2f
#define SCAN_NB ((NN + 255) / 256)   // 196

// ---------------- scratch (__device__ globals; no allocations allowed) -----
__device__ __align__(256) uint4 g_h16[(size_t)NN * 8]; // h fp16: 64 halfs=128B/row
__device__ float    g_asrc[NN];          // h . att_src (fp32)
__device__ float4   g_dinfo[NN];         // (a_dst, sl, start_bits, unused)
__device__ int      g_cnt[NN];           // in-degree (zeroed by agg each run)
__device__ unsigned g_rkd[NE];           // (dst<<16) | rank
__device__ uint2    g_ep[NE];            // per-edge (src, p) dst-sorted
__device__ unsigned g_state[SCAN_NB];    // lookback: state<<30 | value

__device__ __forceinline__ float leaky(float v) { return v > 0.f ? v : SLOPE * v; }

// packed f32x2 helpers (FFMA2 is PTX-only; ptxas never auto-fuses)
__device__ __forceinline__ long long pk2(float lo, float hi) {
    long long r;
    asm("mov.b64 %0, {%1,%2};" : "=l"(r) : "f"(lo), "f"(hi));
    return r;
}
__device__ __forceinline__ void unpk2(long long v, float& lo, float& hi) {
    asm("mov.b64 {%0,%1}, %2;" : "=f"(lo), "=f"(hi) : "l"(v));
}
__device__ __forceinline__ long long ffma2(long long a, long long b, long long c) {
    long long d;
    asm("fma.rn.f32x2 %0, %1, %2, %3;" : "=l"(d) : "l"(a), "l"(b), "l"(c));
    return d;
}

// ---------------------------------------------------------------------------
// K1: dst histogram, 2 edges/thread (int2 loads, 2 independent chains).
//     Stores (dst<<16 | rank). Block 0 resets lookback state.
// ---------------------------------------------------------------------------
__global__ __launch_bounds__(256) void k_count(const int* __restrict__ ei)
{
    if (blockIdx.x == 0 && threadIdx.x < SCAN_NB) g_state[threadIdx.x] = 0;
    int t = blockIdx.x * blockDim.x + threadIdx.x;
    if (t >= NE / 2) return;
    int2 dd = ((const int2*)(ei + NE))[t];
    unsigned r0 = (unsigned)atomicAdd(&g_cnt[dd.x], 1);
    unsigned r1 = (unsigned)atomicAdd(&g_cnt[dd.y], 1);
    int i = t * 2;
    g_rkd[i]     = ((unsigned)dd.x << 16) | (r0 & 0xffffu);
    g_rkd[i + 1] = ((unsigned)dd.y << 16) | (r1 & 0xffffu);
}

// ---------------------------------------------------------------------------
// K2: h = x @ W (packed f32x2 FMAs, 4 rows/warp, 128 threads).
//     Epilogue: fp16 h row, a_src, dst info (a_dst, sl).
// ---------------------------------------------------------------------------
#define GEMM_ROWS 16          // rows per block (4 warps x 4 rows)
__global__ __launch_bounds__(128) void k_gemm(
    const float* __restrict__ x, const float* __restrict__ W,
    const float* __restrict__ att_src, const float* __restrict__ att_dst)
{
    __shared__ long long Wsh[FIN * 32];        // 32 KB
    __shared__ long long Xd[GEMM_ROWS * FIN];  // 16 KB: x duplicated (v,v)

    int tid = threadIdx.x;
    int row0 = blockIdx.x * GEMM_ROWS;

    const float2* W2 = (const float2*)W;
    for (int idx = tid; idx < FIN * 32; idx += 128) {
        float2 wv = W2[idx];
        Wsh[idx] = pk2(wv.x, wv.y);
    }
    for (int idx = tid; idx < GEMM_ROWS * 32; idx += 128) {
        int r = idx >> 5, c = idx & 31;
        int row = row0 + r;
        float4 v = (row < NN) ? ((const float4*)(x + (size_t)row * FIN))[c]
                              : make_float4(0.f, 0.f, 0.f, 0.f);
        long long* dst = &Xd[r * FIN + c * 4];
        dst[0] = pk2(v.x, v.x); dst[1] = pk2(v.y, v.y);
        dst[2] = pk2(v.z, v.z); dst[3] = pk2(v.w, v.w);
    }
    __syncthreads();

    int lane = tid & 31, w = tid >> 5;
    float2 as2 = ((const float2*)att_src)[lane];
    float2 ad2 = ((const float2*)att_dst)[lane];

    long long acc[4] = {0, 0, 0, 0};
    #pragma unroll 4
    for (int k = 0; k < FIN; k += 2) {
        long long w0 = Wsh[k * 32 + lane];
        long long w1 = Wsh[(k + 1) * 32 + lane];
        #pragma unroll
        for (int r = 0; r < 4; r++) {
            longlong2 xx = *(const longlong2*)&Xd[(w * 4 + r) * FIN + k];
            acc[r] = ffma2(xx.x, w0, acc[r]);
            acc[r] = ffma2(xx.y, w1, acc[r]);
        }
    }

    #pragma unroll
    for (int r = 0; r < 4; r++) {
        int row = row0 + w * 4 + r;
        if (row >= NN) continue;
        float a0, a1; unpk2(acc[r], a0, a1);
        ((__half2*)&g_h16[(size_t)row * 8])[lane] = __floats2half2_rn(a0, a1);
        float ps = a0 * as2.x + a1 * as2.y;
        float pd = a0 * ad2.x + a1 * ad2.y;
        #pragma unroll
        for (int off = 16; off; off >>= 1) {
            ps += __shfl_xor_sync(0xffffffffu, ps, off);
            pd += __shfl_xor_sync(0xffffffffu, pd, off);
        }
        if (lane == 0) {
            g_asrc[row] = ps;
            *(float2*)&g_dinfo[row] = make_float2(pd, leaky(ps + pd));
        }
    }
}

// ---------------------------------------------------------------------------
// K3: single-pass exclusive scan (decoupled lookback), 196 blocks.
//     Writes start into g_dinfo[idx].z (int bits).
// ---------------------------------------------------------------------------
__global__ __launch_bounds__(256) void k_scan()
{
    __shared__ int sm[256];
    __shared__ int s_prefix;
    int t = threadIdx.x, b = blockIdx.x;
    int idx = b * 256 + t;
    int v = (idx < NN) ? g_cnt[idx] : 0;
    sm[t] = v;
    __syncthreads();
    #pragma unroll
    for (int off = 1; off < 256; off <<= 1) {
        int u = (t >= off) ? sm[t - off] : 0;
        __syncthreads();
        sm[t] += u;
        __syncthreads();
    }
    int incl = sm[t];
    int agg  = sm[255];

    if (t == 0) {
        if (b == 0) {
            atomicExch(&g_state[0], (2u << 30) | (unsigned)agg);
            s_prefix = 0;
        } else {
            atomicExch(&g_state[b], (1u << 30) | (unsigned)agg);
            int pre = 0, j = b - 1;
            while (true) {
                unsigned s = atomicAdd(&g_state[j], 0u);
                unsigned st = s >> 30;
                if (st == 0u) continue;
                pre += (int)(s & 0x3fffffffu);
                if (st == 2u) break;
                j--;
            }
            s_prefix = pre;
            atomicExch(&g_state[b], (2u << 30) | (unsigned)(pre + agg));
        }
    }
    __syncthreads();
    if (idx < NN) *(int*)&g_dinfo[idx].z = s_prefix + incl - v;
}

// ---------------------------------------------------------------------------
// K4: scatter resolved (src, p) records, 2 edges/thread (2 indep chains).
//     p = exp(leaky(a_src[s] + a_dst[d]) - sl[d])   (fp32, shift-invariant)
// ---------------------------------------------------------------------------
__global__ __launch_bounds__(256) void k_scatter(const int* __restrict__ ei)
{
    int t = blockIdx.x * blockDim.x + threadIdx.x;
    if (t >= NE / 2) return;
    int2  ss = ((const int2*)ei)[t];
    uint2 rd = ((const uint2*)g_rkd)[t];
    int d0 = (int)(rd.x >> 16), r0 = (int)(rd.x & 0xffffu);
    int d1 = (int)(rd.y >> 16), r1 = (int)(rd.y & 0xffffu);
    float4 di0 = g_dinfo[d0];
    float4 di1 = g_dinfo[d1];
    float as0 = g_asrc[ss.x];
    float as1 = g_asrc[ss.y];
    float p0 = __expf(leaky(as0 + di0.x) - di0.y);
    float p1 = __expf(leaky(as1 + di1.x) - di1.y);
    g_ep[__float_as_int(di0.z) + r0] = make_uint2((unsigned)ss.x, __float_as_uint(p0));
    g_ep[__float_as_int(di1.z) + r1] = make_uint2((unsigned)ss.y, __float_as_uint(p1));
}

// ---------------------------------------------------------------------------
// K5: ONE warp per dst node. Lane l owns features (2l, 2l+1) as half2 —
//     matches gemm's store layout. Per edge: one 128B line (32 x LDG.32),
//     zero intra-warp divergence; 8-deep gather unroll + (src,p) prefetch.
//     ssum starts at 1 (self loop), acc starts at h[node]. Zeroes g_cnt.
// ---------------------------------------------------------------------------
__global__ __launch_bounds__(256) void k_agg(float* __restrict__ out,
                                             const float* __restrict__ bias)
{
    int node = (blockIdx.x * 256 + threadIdx.x) >> 5;
    int lane = threadIdx.x & 31;
    if (node >= NN) return;

    float4 di = g_dinfo[node];
    int beg = __float_as_int(di.z);
    int cnt = g_cnt[node];

    const __half2* h2 = (const __half2*)g_h16;   // h2[row*32 + lane]

    float ssum = 1.f;                            // self loop: exp(sl-sl)
    float2 acc = __half22float2(h2[node * 32 + lane]);

    // prefetch batch 0 of (src, p)
    uint2 ev = make_uint2(0u, 0u);
    if (lane < cnt) ev = g_ep[beg + lane];

    for (int base = 0; base < cnt; base += 32) {
        int nb = cnt - base; if (nb > 32) nb = 32;
        unsigned s = ev.x;
        float p = __uint_as_float(ev.y);
        if (lane >= nb) { s = 0u; p = 0.f; }     // padded: p=0, row 0 load ok

        // prefetch next batch of (src, p)
        ev = make_uint2(0u, 0u);
        int nxt = base + 32;
        if (nxt < cnt && lane < cnt - nxt) ev = g_ep[beg + nxt + lane];

        for (int j0 = 0; j0 < nb; j0 += 8) {     // 8 gathers in flight
            __half2 hb[8]; float pp[8];
            #pragma unroll
            for (int u = 0; u < 8; u++) {
                unsigned ss = __shfl_sync(0xffffffffu, s, j0 + u);
                pp[u]       = __shfl_sync(0xffffffffu, p, j0 + u);
                hb[u]       = h2[ss * 32 + lane];      // 128B line per edge
            }
            #pragma unroll
            for (int u = 0; u < 8; u++) {
                float pv = pp[u];                      // 0 beyond nb
                ssum += pv;
                float2 fv = __half22float2(hb[u]);
                acc.x += pv * fv.x;
                acc.y += pv * fv.y;
            }
        }
    }

    float inv = 1.f / ssum;
    float2 bv = ((const float2*)bias)[lane];
    ((float2*)(out + (size_t)node * FOUT))[lane] =
        make_float2(acc.x * inv + bv.x, acc.y * inv + bv.y);
    if (lane == 0) g_cnt[node] = 0;              // ready for next run
}

// ---------------------------------------------------------------------------
extern "C" void kernel_launch(void* const* d_in, const int* in_sizes, int n_in,
                              void* d_out, int out_size)
{
    const float* x    = (const float*)d_in[0];
    const int*   ei   = (const int*)  d_in[1];   // [2, NE]: row0=src, row1=dst
    const float* W    = (const float*)d_in[2];
    const float* asrc = (const float*)d_in[3];
    const float* adst = (const float*)d_in[4];
    const float* bias = (const float*)d_in[5];
    float* out = (float*)d_out;

    static cudaStream_t s1 = nullptr;
    static cudaEvent_t ev_fork = nullptr, ev_join = nullptr;
    if (s1 == nullptr) {
        cudaStreamCreateWithFlags(&s1, cudaStreamNonBlocking);
        cudaEventCreateWithFlags(&ev_fork, cudaEventDisableTiming);
        cudaEventCreateWithFlags(&ev_join, cudaEventDisableTiming);
    }

    // fork: GEMM (x,W only) on s1, concurrent with count+scan (ei only)
    cudaEventRecord(ev_fork, 0);
    cudaStreamWaitEvent(s1, ev_fork, 0);
    k_gemm<<<(NN + GEMM_ROWS - 1) / GEMM_ROWS, 128, 0, s1>>>(x, W, asrc, adst);
    cudaEventRecord(ev_join, s1);

    k_count<<<(NE / 2 + 255) / 256, 256>>>(ei);
    k_scan <<<SCAN_NB, 256>>>();

    cudaStreamWaitEvent(0, ev_join, 0);          // scatter needs GEMM outputs
    k_scatter<<<(NE / 2 + 255) / 256, 256>>>(ei);
    k_agg<<<(NN * 32 + 255) / 256, 256>>>(out, bias);
}